// round 15
// baseline (speedup 1.0000x reference)
#include <cuda_runtime.h>
#include <cstdint>

#define G_   2048
#define NPG  128
#define NN   (G_*NPG)       // 262144 nodes
#define INC  151
#define HID  64
#define NE   2097152
#define NEG_SLOPE 0.2f
#define ECAP 1536           // per-graph staged edge cap (mean 1024, sigma ~32)

// ---------------- device scratch ----------------
__device__ float g_h[(size_t)NN * HID];   // 64 MB
__device__ float g_as[NN];
__device__ float g_ad[NN];
__device__ int   g_deg[NN];
__device__ int   g_fill[NN];
__device__ int   g_off[NN];
__device__ int   g_bsum[1024];
__device__ int   g_csr[NE];

// ---------------- K0: zero counters ----------------
__global__ void k_zero() {
    int i = blockIdx.x * blockDim.x + threadIdx.x;
    g_deg[i] = 0; g_fill[i] = 0;
}

// ---------------- K1: h = x @ W1 fp32 SIMT, 8x8 microtile, double-buffered ----
// 9 full chunks of k=16 + tail chunk of k=7 (151 total, no phantom FFMA).
#define LDX 132
#define LDW 68
#define NCH 10
__global__ __launch_bounds__(128) void k_gemm(const float* __restrict__ x,
                                              const float* __restrict__ W,
                                              const float* __restrict__ att_src,
                                              const float* __restrict__ att_dst) {
    __shared__ float sX[2][16 * LDX];   // [buf][k][row]
    __shared__ float sW[2][16 * LDW];   // [buf][k][col]
    int tid = threadIdx.x;
    int tx = tid & 7, ty = tid >> 3;
    int row0 = blockIdx.x * 128;

    int cx = tid & 15, rt = tid >> 4;     // sX staging coords
    int nn = tid & 63, kt = tid >> 6;     // sW staging coords

    float rx[16], rw[8];

    #define LOADC(ch) do {                                                   \
        int col = (ch) * 16 + cx;                                            \
        bool ok = (col < INC);                                               \
        _Pragma("unroll")                                                    \
        for (int p = 0; p < 16; p++) {                                       \
            int r = rt + p * 8;                                              \
            rx[p] = ok ? x[(size_t)(row0 + r) * INC + col] : 0.f;            \
        }                                                                    \
        _Pragma("unroll")                                                    \
        for (int p = 0; p < 8; p++) {                                        \
            int kk = (ch) * 16 + kt + p * 2;                                 \
            rw[p] = (kk < INC) ? W[kk * 64 + nn] : 0.f;                      \
        }                                                                    \
    } while (0)

    #define STOREC(buf) do {                                                 \
        _Pragma("unroll")                                                    \
        for (int p = 0; p < 16; p++) sX[buf][cx * LDX + rt + p * 8] = rx[p]; \
        _Pragma("unroll")                                                    \
        for (int p = 0; p < 8; p++) sW[buf][(kt + p * 2) * LDW + nn] = rw[p];\
    } while (0)

    #define COMPUTE(cur, KMAX) do {                                          \
        _Pragma("unroll")                                                    \
        for (int k = 0; k < (KMAX); k++) {                                   \
            float4 a0 = *(const float4*)&sX[cur][k * LDX + ty * 4];          \
            float4 a1 = *(const float4*)&sX[cur][k * LDX + 64 + ty * 4];     \
            float4 b0 = *(const float4*)&sW[cur][k * LDW + tx * 4];          \
            float4 b1 = *(const float4*)&sW[cur][k * LDW + 32 + tx * 4];     \
            float av[8] = {a0.x, a0.y, a0.z, a0.w, a1.x, a1.y, a1.z, a1.w};  \
            float bv[8] = {b0.x, b0.y, b0.z, b0.w, b1.x, b1.y, b1.z, b1.w};  \
            _Pragma("unroll")                                                \
            for (int i = 0; i < 8; i++)                                      \
                _Pragma("unroll")                                            \
                for (int j = 0; j < 8; j++)                                  \
                    acc[i][j] = fmaf(av[i], bv[j], acc[i][j]);               \
        }                                                                    \
    } while (0)

    float acc[8][8];
    #pragma unroll
    for (int i = 0; i < 8; i++)
        #pragma unroll
        for (int j = 0; j < 8; j++) acc[i][j] = 0.f;

    LOADC(0);
    STOREC(0);
    __syncthreads();
    LOADC(1);

    for (int ch = 0; ch < NCH - 1; ch++) {      // chunks 0..8: full k=16
        int cur = ch & 1;
        STOREC(cur ^ 1);                        // regs hold chunk ch+1
        if (ch < NCH - 2) LOADC(ch + 2);
        COMPUTE(cur, 16);
        __syncthreads();
    }
    // tail chunk 9: only 7 real k (cols 144..150)
    COMPUTE((NCH - 1) & 1, 7);

    float asv[8], adv[8];
    #pragma unroll
    for (int j = 0; j < 8; j++) {
        int cj = (j < 4) ? (tx * 4 + j) : (32 + tx * 4 + (j - 4));
        asv[j] = __ldg(&att_src[cj]);
        adv[j] = __ldg(&att_dst[cj]);
    }

    #pragma unroll
    for (int i = 0; i < 8; i++) {
        int r = row0 + ((i < 4) ? (ty * 4 + i) : (64 + ty * 4 + (i - 4)));
        float4 lo = make_float4(acc[i][0], acc[i][1], acc[i][2], acc[i][3]);
        float4 hi = make_float4(acc[i][4], acc[i][5], acc[i][6], acc[i][7]);
        *(float4*)&g_h[(size_t)r * 64 + tx * 4]      = lo;
        *(float4*)&g_h[(size_t)r * 64 + 32 + tx * 4] = hi;
        float ps = 0.f, pd = 0.f;
        #pragma unroll
        for (int j = 0; j < 8; j++) {
            ps = fmaf(acc[i][j], asv[j], ps);
            pd = fmaf(acc[i][j], adv[j], pd);
        }
        #pragma unroll
        for (int o = 4; o; o >>= 1) {
            ps += __shfl_down_sync(0xFFFFFFFFu, ps, o, 8);
            pd += __shfl_down_sync(0xFFFFFFFFu, pd, o, 8);
        }
        if (tx == 0) { g_as[r] = ps; g_ad[r] = pd; }
    }
}

// ---------------- K2: in-degree histogram ----------------
__global__ void k_hist(const int* __restrict__ ei) {
    int e = blockIdx.x * blockDim.x + threadIdx.x;
    if (e < NE) atomicAdd(&g_deg[ei[NE + e]], 1);
}

// ---------------- K3: 2-level exclusive scan ----------------
__global__ void k_scanA() {
    int t = threadIdx.x;
    int i = blockIdx.x * 256 + t;
    int v = g_deg[i];
    int lane = t & 31, w = t >> 5;
    int x = v;
    #pragma unroll
    for (int d = 1; d < 32; d <<= 1) { int y = __shfl_up_sync(0xFFFFFFFFu, x, d); if (lane >= d) x += y; }
    __shared__ int wt[8];
    if (lane == 31) wt[w] = x;
    __syncthreads();
    if (t < 8) {
        int s = wt[t];
        int xs = s;
        #pragma unroll
        for (int d = 1; d < 8; d <<= 1) { int y = __shfl_up_sync(0xFFu, xs, d); if (t >= d) xs += y; }
        wt[t] = xs - s;
    }
    __syncthreads();
    int incl = x + wt[w];
    g_off[i] = incl - v;
    if (t == 255) g_bsum[blockIdx.x] = incl;
}

__global__ void k_scanB() {
    int t = threadIdx.x;
    int lane = t & 31, w = t >> 5;
    int v = g_bsum[t];
    int x = v;
    #pragma unroll
    for (int d = 1; d < 32; d <<= 1) { int y = __shfl_up_sync(0xFFFFFFFFu, x, d); if (lane >= d) x += y; }
    __shared__ int wt[32];
    if (lane == 31) wt[w] = x;
    __syncthreads();
    if (w == 0) {
        int s = wt[lane];
        int xs = s;
        #pragma unroll
        for (int d = 1; d < 32; d <<= 1) { int y = __shfl_up_sync(0xFFFFFFFFu, xs, d); if (lane >= d) xs += y; }
        wt[lane] = xs - s;
    }
    __syncthreads();
    g_bsum[t] = x - v + wt[w];
}

__global__ void k_scanC() {
    int i = blockIdx.x * 256 + threadIdx.x;
    g_off[i] += g_bsum[i >> 8];
}

// ---------------- K4: scatter into CSR ----------------
__global__ void k_scatter(const int* __restrict__ ei) {
    int e = blockIdx.x * blockDim.x + threadIdx.x;
    if (e >= NE) return;
    int dst = ei[NE + e];
    int src = ei[e];
    int p = g_off[dst] + atomicAdd(&g_fill[dst], 1);
    g_csr[p] = src;
}

// ---------------- K5: block-per-graph, fully smem-staged softmax agg ----------
__global__ __launch_bounds__(256) void k_agg(const float* __restrict__ b1,
                                             const float* __restrict__ Wlin,
                                             const float* __restrict__ blin,
                                             float* __restrict__ out) {
    __shared__ float sh[128 * 64];        // 32 KB graph h tile
    __shared__ float s_as[128], s_ad[128];
    __shared__ int   s_off[128];
    __shared__ int   s_deg[128];
    __shared__ int   s_csr[ECAP];
    __shared__ float s_w[ECAP];
    __shared__ float s_w0[128];
    __shared__ float s_part[8];
    int g = blockIdx.x;
    int tid = threadIdx.x, lane = tid & 31, wid = tid >> 5;
    int nbase = g * 128;

    {
        const float4* src4 = (const float4*)&g_h[(size_t)nbase * 64];
        float4* dst4 = (float4*)sh;
        #pragma unroll
        for (int i = tid; i < 128 * 16; i += 256) dst4[i] = src4[i];
        if (tid < 128) {
            s_as[tid] = g_as[nbase + tid];
            s_ad[tid] = g_ad[nbase + tid];
            s_deg[tid] = g_deg[nbase + tid];
        }
    }
    int e0 = __ldg(&g_off[nbase]);
    int eend = (g == G_ - 1) ? NE : __ldg(&g_off[nbase + 128]);
    int ecnt = eend - e0;
    if (tid < 128) s_off[tid] = g_off[nbase + tid] - e0;
    for (int i = tid; i < ecnt && i < ECAP; i += 256) s_csr[i] = g_csr[e0 + i] & 127;
    __syncthreads();

    if (tid < 128) {
        int ln = tid;
        float ad_i = s_ad[ln];
        int deg = s_deg[ln], eb = s_off[ln];
        float a0 = s_as[ln] + ad_i;
        a0 = a0 >= 0.f ? a0 : NEG_SLOPE * a0;
        float m = a0;
        for (int e = 0; e < deg; e++) {
            int idx = eb + e;
            int s = (idx < ECAP) ? s_csr[idx] : (g_csr[e0 + idx] & 127);
            float a = s_as[s] + ad_i;
            a = a >= 0.f ? a : NEG_SLOPE * a;
            m = fmaxf(m, a);
        }
        float z = __expf(a0 - m);
        for (int e = 0; e < deg; e++) {
            int idx = eb + e;
            int s = (idx < ECAP) ? s_csr[idx] : (g_csr[e0 + idx] & 127);
            float a = s_as[s] + ad_i;
            a = a >= 0.f ? a : NEG_SLOPE * a;
            float ex = __expf(a - m);
            if (idx < ECAP) s_w[idx] = ex;
            z += ex;
        }
        float invz = 1.f / z;
        s_w0[ln] = __expf(a0 - m) * invz;
        for (int e = 0; e < deg; e++) {
            int idx = eb + e;
            if (idx < ECAP) s_w[idx] *= invz;
        }
    }
    __syncthreads();

    float2 bb = *(const float2*)&b1[lane * 2];
    float wsum = 0.f;

    for (int t = 0; t < 16; t++) {
        int ln = wid * 16 + t;
        int deg = s_deg[ln], eb = s_off[ln];
        float2 hme = *(const float2*)&sh[ln * 64 + lane * 2];
        float w0 = s_w0[ln];
        float accx = w0 * hme.x, accy = w0 * hme.y;
        for (int e = 0; e < deg; e++) {
            int idx = eb + e;
            int s;
            float w;
            if (idx < ECAP) { s = s_csr[idx]; w = s_w[idx]; }
            else {
                s = g_csr[e0 + idx] & 127;
                float ad_i = s_ad[ln];
                float a = s_as[s] + ad_i;
                a = a >= 0.f ? a : NEG_SLOPE * a;
                float a0 = s_as[ln] + ad_i;
                a0 = a0 >= 0.f ? a0 : NEG_SLOPE * a0;
                float m = a0;
                for (int e2 = 0; e2 < deg; e2++) {
                    int s2 = g_csr[e0 + eb + e2] & 127;
                    float a2 = s_as[s2] + ad_i;
                    a2 = a2 >= 0.f ? a2 : NEG_SLOPE * a2;
                    m = fmaxf(m, a2);
                }
                float z = __expf(a0 - m);
                for (int e2 = 0; e2 < deg; e2++) {
                    int s2 = g_csr[e0 + eb + e2] & 127;
                    float a2 = s_as[s2] + ad_i;
                    a2 = a2 >= 0.f ? a2 : NEG_SLOPE * a2;
                    z += __expf(a2 - m);
                }
                w = __expf(a - m) / z;
            }
            float2 hs = *(const float2*)&sh[s * 64 + lane * 2];
            accx = fmaf(w, hs.x, accx);
            accy = fmaf(w, hs.y, accy);
        }

        float rx = fmaxf(accx + bb.x, 0.f);
        float ry = fmaxf(accy + bb.y, 0.f);
        float2 wl = *(const float2*)&Wlin[ln * 64 + lane * 2];
        float p = rx * wl.x + ry * wl.y;
        #pragma unroll
        for (int o = 16; o; o >>= 1) p += __shfl_xor_sync(0xFFFFFFFFu, p, o);
        wsum += p;
    }

    if (lane == 0) s_part[wid] = wsum;
    __syncthreads();
    if (tid == 0) {
        float l = blin[0];
        #pragma unroll
        for (int i = 0; i < 8; i++) l += s_part[i];
        out[g] = 1.f / (1.f + __expf(-l));
    }
}

// ---------------- launch ----------------
extern "C" void kernel_launch(void* const* d_in, const int* in_sizes, int n_in,
                              void* d_out, int out_size) {
    const float* x    = (const float*)d_in[0];
    const int*   ei   = (const int*)  d_in[1];
    const float* W1   = (const float*)d_in[2];
    const float* asv  = (const float*)d_in[3];
    const float* adv  = (const float*)d_in[4];
    const float* b1   = (const float*)d_in[5];
    const float* Wlin = (const float*)d_in[6];
    const float* blin = (const float*)d_in[7];
    float* out = (float*)d_out;

    static cudaStream_t s2 = nullptr;
    static cudaEvent_t ev0 = nullptr, ev1 = nullptr;
    if (!s2) {
        cudaStreamCreateWithFlags(&s2, cudaStreamNonBlocking);
        cudaEventCreateWithFlags(&ev0, cudaEventDisableTiming);
        cudaEventCreateWithFlags(&ev1, cudaEventDisableTiming);
    }

    // fork: zero + edge preprocessing on side stream, overlapped with GEMM
    cudaEventRecord(ev0, 0);
    cudaStreamWaitEvent(s2, ev0, 0);
    k_zero   <<<NN / 256, 256, 0, s2>>>();
    k_hist   <<<NE / 256, 256, 0, s2>>>(ei);
    k_scanA  <<<1024, 256, 0, s2>>>();
    k_scanB  <<<1, 1024, 0, s2>>>();
    k_scanC  <<<1024, 256, 0, s2>>>();
    k_scatter<<<NE / 256, 256, 0, s2>>>(ei);
    cudaEventRecord(ev1, s2);

    k_gemm<<<NN / 128, 128>>>(x, W1, asv, adv);

    // join
    cudaStreamWaitEvent(0, ev1, 0);
    k_agg<<<G_, 256>>>(b1, Wlin, blin, out);
}

// round 16
// speedup vs baseline: 1.0801x; 1.0801x over previous
#include <cuda_runtime.h>
#include <cstdint>

#define G_   2048
#define NPG  128
#define NN   (G_*NPG)       // 262144 nodes
#define INC  151
#define HID  64
#define NE   2097152
#define NEG_SLOPE 0.2f
#define ECAP 1536           // per-graph staged edge cap (mean 1024, sigma ~32)

// ---------------- device scratch ----------------
__device__ float g_h[(size_t)NN * HID];   // 64 MB
__device__ float g_as[NN];
__device__ float g_ad[NN];
__device__ int   g_deg[NN];
__device__ int   g_fill[NN];
__device__ int   g_off[NN];
__device__ int   g_bsum[1024];
__device__ int   g_csr[NE];

// ---------------- K0: zero counters ----------------
__global__ void k_zero() {
    int i = blockIdx.x * blockDim.x + threadIdx.x;
    g_deg[i] = 0; g_fill[i] = 0;
}

// ---------------- K1: h = x @ W1 fp32 SIMT, 8x8 microtile, double-buffered ----
// (exact R14 GEMM — 279us version; do not touch)
#define LDX 132
#define LDW 68
#define NCH 10
__global__ __launch_bounds__(128) void k_gemm(const float* __restrict__ x,
                                              const float* __restrict__ W,
                                              const float* __restrict__ att_src,
                                              const float* __restrict__ att_dst) {
    __shared__ float sX[2][16 * LDX];   // [buf][k][row]
    __shared__ float sW[2][16 * LDW];   // [buf][k][col]
    int tid = threadIdx.x;
    int tx = tid & 7, ty = tid >> 3;
    int row0 = blockIdx.x * 128;

    int cx = tid & 15, rt = tid >> 4;     // sX staging coords
    int nn = tid & 63, kt = tid >> 6;     // sW staging coords

    float rx[16], rw[8];

    #define LOADC(ch) do {                                                   \
        int col = (ch) * 16 + cx;                                            \
        bool ok = (col < INC);                                               \
        _Pragma("unroll")                                                    \
        for (int p = 0; p < 16; p++) {                                       \
            int r = rt + p * 8;                                              \
            rx[p] = ok ? x[(size_t)(row0 + r) * INC + col] : 0.f;            \
        }                                                                    \
        _Pragma("unroll")                                                    \
        for (int p = 0; p < 8; p++) {                                        \
            int kk = (ch) * 16 + kt + p * 2;                                 \
            rw[p] = (kk < INC) ? W[kk * 64 + nn] : 0.f;                      \
        }                                                                    \
    } while (0)

    #define STOREC(buf) do {                                                 \
        _Pragma("unroll")                                                    \
        for (int p = 0; p < 16; p++) sX[buf][cx * LDX + rt + p * 8] = rx[p]; \
        _Pragma("unroll")                                                    \
        for (int p = 0; p < 8; p++) sW[buf][(kt + p * 2) * LDW + nn] = rw[p];\
    } while (0)

    float acc[8][8];
    #pragma unroll
    for (int i = 0; i < 8; i++)
        #pragma unroll
        for (int j = 0; j < 8; j++) acc[i][j] = 0.f;

    LOADC(0);
    STOREC(0);
    __syncthreads();
    LOADC(1);

    for (int ch = 0; ch < NCH; ch++) {
        int cur = ch & 1;
        if (ch < NCH - 1) STOREC(cur ^ 1);     // regs hold chunk ch+1
        if (ch < NCH - 2) LOADC(ch + 2);       // LDG in flight during compute
        #pragma unroll
        for (int k = 0; k < 16; k++) {
            float4 a0 = *(const float4*)&sX[cur][k * LDX + ty * 4];
            float4 a1 = *(const float4*)&sX[cur][k * LDX + 64 + ty * 4];
            float4 b0 = *(const float4*)&sW[cur][k * LDW + tx * 4];
            float4 b1 = *(const float4*)&sW[cur][k * LDW + 32 + tx * 4];
            float av[8] = {a0.x, a0.y, a0.z, a0.w, a1.x, a1.y, a1.z, a1.w};
            float bv[8] = {b0.x, b0.y, b0.z, b0.w, b1.x, b1.y, b1.z, b1.w};
            #pragma unroll
            for (int i = 0; i < 8; i++)
                #pragma unroll
                for (int j = 0; j < 8; j++)
                    acc[i][j] = fmaf(av[i], bv[j], acc[i][j]);
        }
        __syncthreads();
    }

    float asv[8], adv[8];
    #pragma unroll
    for (int j = 0; j < 8; j++) {
        int cj = (j < 4) ? (tx * 4 + j) : (32 + tx * 4 + (j - 4));
        asv[j] = __ldg(&att_src[cj]);
        adv[j] = __ldg(&att_dst[cj]);
    }

    #pragma unroll
    for (int i = 0; i < 8; i++) {
        int r = row0 + ((i < 4) ? (ty * 4 + i) : (64 + ty * 4 + (i - 4)));
        float4 lo = make_float4(acc[i][0], acc[i][1], acc[i][2], acc[i][3]);
        float4 hi = make_float4(acc[i][4], acc[i][5], acc[i][6], acc[i][7]);
        *(float4*)&g_h[(size_t)r * 64 + tx * 4]      = lo;
        *(float4*)&g_h[(size_t)r * 64 + 32 + tx * 4] = hi;
        float ps = 0.f, pd = 0.f;
        #pragma unroll
        for (int j = 0; j < 8; j++) {
            ps = fmaf(acc[i][j], asv[j], ps);
            pd = fmaf(acc[i][j], adv[j], pd);
        }
        #pragma unroll
        for (int o = 4; o; o >>= 1) {
            ps += __shfl_down_sync(0xFFFFFFFFu, ps, o, 8);
            pd += __shfl_down_sync(0xFFFFFFFFu, pd, o, 8);
        }
        if (tx == 0) { g_as[r] = ps; g_ad[r] = pd; }
    }
}

// ---------------- K2: in-degree histogram ----------------
__global__ void k_hist(const int* __restrict__ ei) {
    int e = blockIdx.x * blockDim.x + threadIdx.x;
    if (e < NE) atomicAdd(&g_deg[ei[NE + e]], 1);
}

// ---------------- K3: 2-level exclusive scan ----------------
__global__ void k_scanA() {
    int t = threadIdx.x;
    int i = blockIdx.x * 256 + t;
    int v = g_deg[i];
    int lane = t & 31, w = t >> 5;
    int x = v;
    #pragma unroll
    for (int d = 1; d < 32; d <<= 1) { int y = __shfl_up_sync(0xFFFFFFFFu, x, d); if (lane >= d) x += y; }
    __shared__ int wt[8];
    if (lane == 31) wt[w] = x;
    __syncthreads();
    if (t < 8) {
        int s = wt[t];
        int xs = s;
        #pragma unroll
        for (int d = 1; d < 8; d <<= 1) { int y = __shfl_up_sync(0xFFu, xs, d); if (t >= d) xs += y; }
        wt[t] = xs - s;
    }
    __syncthreads();
    int incl = x + wt[w];
    g_off[i] = incl - v;
    if (t == 255) g_bsum[blockIdx.x] = incl;
}

__global__ void k_scanB() {
    int t = threadIdx.x;
    int lane = t & 31, w = t >> 5;
    int v = g_bsum[t];
    int x = v;
    #pragma unroll
    for (int d = 1; d < 32; d <<= 1) { int y = __shfl_up_sync(0xFFFFFFFFu, x, d); if (lane >= d) x += y; }
    __shared__ int wt[32];
    if (lane == 31) wt[w] = x;
    __syncthreads();
    if (w == 0) {
        int s = wt[lane];
        int xs = s;
        #pragma unroll
        for (int d = 1; d < 32; d <<= 1) { int y = __shfl_up_sync(0xFFFFFFFFu, xs, d); if (lane >= d) xs += y; }
        wt[lane] = xs - s;
    }
    __syncthreads();
    g_bsum[t] = x - v + wt[w];
}

__global__ void k_scanC() {
    int i = blockIdx.x * 256 + threadIdx.x;
    g_off[i] += g_bsum[i >> 8];
}

// ---------------- K4: scatter into CSR ----------------
__global__ void k_scatter(const int* __restrict__ ei) {
    int e = blockIdx.x * blockDim.x + threadIdx.x;
    if (e >= NE) return;
    int dst = ei[NE + e];
    int src = ei[e];
    int p = g_off[dst] + atomicAdd(&g_fill[dst], 1);
    g_csr[p] = src;
}

// ---------------- K5: block-per-graph agg, no-max softmax, packed (src,w) ----
__global__ __launch_bounds__(256) void k_agg(const float* __restrict__ b1,
                                             const float* __restrict__ Wlin,
                                             const float* __restrict__ blin,
                                             float* __restrict__ out) {
    __shared__ float sh[128 * 64];        // 32 KB graph h tile
    __shared__ float s_as[128], s_ad[128];
    __shared__ int   s_off[128];
    __shared__ int   s_deg[128];
    __shared__ int2  s_ew[ECAP];          // .x = src local id, .y = bits(weight)
    __shared__ float s_w0[128];           // normalized self-loop weight
    __shared__ float s_invz[128];         // per-node 1/z (for overflow path)
    __shared__ float s_part[8];
    int g = blockIdx.x;
    int tid = threadIdx.x, lane = tid & 31, wid = tid >> 5;
    int nbase = g * 128;

    // stage h tile + scores + per-node ranges
    {
        const float4* src4 = (const float4*)&g_h[(size_t)nbase * 64];
        float4* dst4 = (float4*)sh;
        #pragma unroll
        for (int i = tid; i < 128 * 16; i += 256) dst4[i] = src4[i];
        if (tid < 128) {
            s_as[tid] = g_as[nbase + tid];
            s_ad[tid] = g_ad[nbase + tid];
            s_deg[tid] = g_deg[nbase + tid];
        }
    }
    int e0 = __ldg(&g_off[nbase]);
    int eend = (g == G_ - 1) ? NE : __ldg(&g_off[nbase + 128]);
    int ecnt = eend - e0;
    if (tid < 128) s_off[tid] = g_off[nbase + tid] - e0;
    for (int i = tid; i < ecnt && i < ECAP; i += 256) s_ew[i].x = g_csr[e0 + i] & 127;
    __syncthreads();

    // thread-per-node: softmax WITHOUT max shift (scores bounded ~|12|, exp-safe)
    if (tid < 128) {
        int ln = tid;
        float ad_i = s_ad[ln];
        int deg = s_deg[ln], eb = s_off[ln];
        float a0 = s_as[ln] + ad_i;
        a0 = a0 >= 0.f ? a0 : NEG_SLOPE * a0;
        float e_self = __expf(a0);
        float z = e_self;
        for (int e = 0; e < deg; e++) {
            int idx = eb + e;
            int s = (idx < ECAP) ? s_ew[idx].x : (g_csr[e0 + idx] & 127);
            float a = s_as[s] + ad_i;
            a = a >= 0.f ? a : NEG_SLOPE * a;
            float ex = __expf(a);
            if (idx < ECAP) s_ew[idx].y = __float_as_int(ex);
            z += ex;
        }
        float invz = 1.f / z;
        s_invz[ln] = invz;
        s_w0[ln] = e_self * invz;
        for (int e = 0; e < deg; e++) {
            int idx = eb + e;
            if (idx < ECAP)
                s_ew[idx].y = __float_as_int(__int_as_float(s_ew[idx].y) * invz);
        }
    }
    __syncthreads();

    float2 bb = *(const float2*)&b1[lane * 2];
    float wsum = 0.f;

    for (int t = 0; t < 16; t++) {
        int ln = wid * 16 + t;
        int deg = s_deg[ln], eb = s_off[ln];
        float2 hme = *(const float2*)&sh[ln * 64 + lane * 2];
        float w0 = s_w0[ln];
        float accx = w0 * hme.x, accy = w0 * hme.y;
        for (int e = 0; e < deg; e++) {
            int idx = eb + e;
            int s;
            float w;
            if (idx < ECAP) {
                int2 ew = s_ew[idx];          // single LDS.64 broadcast
                s = ew.x;
                w = __int_as_float(ew.y);
            } else {
                // rare overflow: w = exp(a) * invz directly
                s = g_csr[e0 + idx] & 127;
                float a = s_as[s] + s_ad[ln];
                a = a >= 0.f ? a : NEG_SLOPE * a;
                w = __expf(a) * s_invz[ln];
            }
            float2 hs = *(const float2*)&sh[s * 64 + lane * 2];
            accx = fmaf(w, hs.x, accx);
            accy = fmaf(w, hs.y, accy);
        }

        float rx = fmaxf(accx + bb.x, 0.f);
        float ry = fmaxf(accy + bb.y, 0.f);
        float2 wl = *(const float2*)&Wlin[ln * 64 + lane * 2];
        float p = rx * wl.x + ry * wl.y;
        #pragma unroll
        for (int o = 16; o; o >>= 1) p += __shfl_xor_sync(0xFFFFFFFFu, p, o);
        wsum += p;
    }

    if (lane == 0) s_part[wid] = wsum;
    __syncthreads();
    if (tid == 0) {
        float l = blin[0];
        #pragma unroll
        for (int i = 0; i < 8; i++) l += s_part[i];
        out[g] = 1.f / (1.f + __expf(-l));
    }
}

// ---------------- launch ----------------
extern "C" void kernel_launch(void* const* d_in, const int* in_sizes, int n_in,
                              void* d_out, int out_size) {
    const float* x    = (const float*)d_in[0];
    const int*   ei   = (const int*)  d_in[1];
    const float* W1   = (const float*)d_in[2];
    const float* asv  = (const float*)d_in[3];
    const float* adv  = (const float*)d_in[4];
    const float* b1   = (const float*)d_in[5];
    const float* Wlin = (const float*)d_in[6];
    const float* blin = (const float*)d_in[7];
    float* out = (float*)d_out;

    static cudaStream_t s2 = nullptr;
    static cudaEvent_t ev0 = nullptr, ev1 = nullptr;
    if (!s2) {
        cudaStreamCreateWithFlags(&s2, cudaStreamNonBlocking);
        cudaEventCreateWithFlags(&ev0, cudaEventDisableTiming);
        cudaEventCreateWithFlags(&ev1, cudaEventDisableTiming);
    }

    // fork: zero + edge preprocessing on side stream, overlapped with GEMM
    cudaEventRecord(ev0, 0);
    cudaStreamWaitEvent(s2, ev0, 0);
    k_zero   <<<NN / 256, 256, 0, s2>>>();
    k_hist   <<<NE / 256, 256, 0, s2>>>(ei);
    k_scanA  <<<1024, 256, 0, s2>>>();
    k_scanB  <<<1, 1024, 0, s2>>>();
    k_scanC  <<<1024, 256, 0, s2>>>();
    k_scatter<<<NE / 256, 256, 0, s2>>>(ei);
    cudaEventRecord(ev1, s2);

    k_gemm<<<NN / 128, 128>>>(x, W1, asv, adv);

    // join
    cudaStreamWaitEvent(0, ev1, 0);
    k_agg<<<G_, 256>>>(b1, Wlin, blin, out);
}